// round 9
// baseline (speedup 1.0000x reference)
#include <cuda_runtime.h>

// Attention: B=2, H=16, S=2048, D=64 (fp32), mask int32 [B,1,S,S]
// Outputs concatenated in d_out: out [B,H,S,D] then p_attn [B,H,S,S].
//
// Per (b,h, qtile=128) block, 256 threads:
//   Pass 1: 128x128 QK^T tiles (8x8 microtile) -> raw masked scores to p_attn,
//           flash-style online (m, l) in registers; per-row m, 1/l parked in smem.
//   Pass 2: cooperative re-read of scores, finalize p = exp(s-m)/l (overwrite
//           p_attn), stage p in natural [q][k] smem, out += p @ V (4x8 microtile).

#define S_LEN 2048
#define D_HEAD 64
#define TQ 128

__global__ __launch_bounds__(256, 2)
void attn_kernel(const float* __restrict__ Q,
                 const float* __restrict__ K,
                 const float* __restrict__ V,
                 const int*   __restrict__ M,
                 float* __restrict__ Out,
                 float* __restrict__ P)
{
    extern __shared__ float sm[];
    float* sMx = sm;         // [128] row max
    float* sLi = sm + 128;   // [128] 1/l
    float* s0  = sm + 256;
    // pass1 union: sQt [64][132], sKt [64][132]
    // pass2 union: sP  [128][132], sV [128][68]
    float* sQt = s0;
    float* sKt = s0 + 64 * 132;
    float* sP  = s0;
    float* sV  = s0 + 128 * 132;

    const int tid = threadIdx.x;
    const int tx  = tid & 15;     // pass1: k-col group
    const int ty  = tid >> 4;     // pass1: q-row group
    const int bh  = blockIdx.y;
    const int q0  = blockIdx.x * TQ;

    const float* qp = Q + ((size_t)bh * S_LEN + q0) * D_HEAD;
    const float* kp = K + (size_t)bh * S_LEN * D_HEAD;
    const float* vp = V + (size_t)bh * S_LEN * D_HEAD;
    const int*   mp = M + (size_t)(bh >> 4) * S_LEN * S_LEN + (size_t)q0 * S_LEN;
    float* pp = P   + ((size_t)bh * S_LEN + q0) * S_LEN;
    float* op = Out + ((size_t)bh * S_LEN + q0) * D_HEAD;

    // ---- load Q tile (128x64) transposed into sQt[d][q] ----
    {
        const int c = tx * 4;
        #pragma unroll
        for (int it = 0; it < 8; ++it) {
            const int row = ty + it * 16;
            float4 v = *(const float4*)(qp + row * D_HEAD + c);
            sQt[(c + 0) * 132 + row] = v.x;
            sQt[(c + 1) * 132 + row] = v.y;
            sQt[(c + 2) * 132 + row] = v.z;
            sQt[(c + 3) * 132 + row] = v.w;
        }
    }

    float m_run[8], l_run[8];
    #pragma unroll
    for (int i = 0; i < 8; ++i) { m_run[i] = -3.0e38f; l_run[i] = 0.0f; }

    // ================= Pass 1: scores + online stats =================
    for (int kt = 0; kt < S_LEN; kt += 128) {
        __syncthreads();
        // load K tile (128x64) transposed into sKt[d][k]
        {
            const int c = tx * 4;
            #pragma unroll
            for (int it = 0; it < 8; ++it) {
                const int row = ty + it * 16;
                float4 v = *(const float4*)(kp + (size_t)(kt + row) * D_HEAD + c);
                sKt[(c + 0) * 132 + row] = v.x;
                sKt[(c + 1) * 132 + row] = v.y;
                sKt[(c + 2) * 132 + row] = v.z;
                sKt[(c + 3) * 132 + row] = v.w;
            }
        }
        __syncthreads();

        float acc[8][8];
        #pragma unroll
        for (int i = 0; i < 8; ++i)
            #pragma unroll
            for (int j = 0; j < 8; ++j) acc[i][j] = 0.0f;

        #pragma unroll 8
        for (int d = 0; d < 64; ++d) {
            float4 a0 = *(const float4*)(sQt + d * 132 + 8 * ty);
            float4 a1 = *(const float4*)(sQt + d * 132 + 8 * ty + 4);
            float4 b0 = *(const float4*)(sKt + d * 132 + 4 * tx);
            float4 b1 = *(const float4*)(sKt + d * 132 + 64 + 4 * tx);
            const float av[8] = {a0.x, a0.y, a0.z, a0.w, a1.x, a1.y, a1.z, a1.w};
            const float bv[8] = {b0.x, b0.y, b0.z, b0.w, b1.x, b1.y, b1.z, b1.w};
            #pragma unroll
            for (int i = 0; i < 8; ++i)
                #pragma unroll
                for (int j = 0; j < 8; ++j)
                    acc[i][j] += av[i] * bv[j];
        }

        #pragma unroll
        for (int i = 0; i < 8; ++i) {
            const int qr = 8 * ty + i;
            const int4 mv0 = *(const int4*)(mp + (size_t)qr * S_LEN + kt + 4 * tx);
            const int4 mv1 = *(const int4*)(mp + (size_t)qr * S_LEN + kt + 64 + 4 * tx);
            float s[8];
            s[0] = mv0.x ? acc[i][0] * 0.125f : -1.0e9f;
            s[1] = mv0.y ? acc[i][1] * 0.125f : -1.0e9f;
            s[2] = mv0.z ? acc[i][2] * 0.125f : -1.0e9f;
            s[3] = mv0.w ? acc[i][3] * 0.125f : -1.0e9f;
            s[4] = mv1.x ? acc[i][4] * 0.125f : -1.0e9f;
            s[5] = mv1.y ? acc[i][5] * 0.125f : -1.0e9f;
            s[6] = mv1.z ? acc[i][6] * 0.125f : -1.0e9f;
            s[7] = mv1.w ? acc[i][7] * 0.125f : -1.0e9f;
            *(float4*)(pp + (size_t)qr * S_LEN + kt + 4 * tx) =
                make_float4(s[0], s[1], s[2], s[3]);
            *(float4*)(pp + (size_t)qr * S_LEN + kt + 64 + 4 * tx) =
                make_float4(s[4], s[5], s[6], s[7]);

            float tmax = fmaxf(fmaxf(fmaxf(s[0], s[1]), fmaxf(s[2], s[3])),
                               fmaxf(fmaxf(s[4], s[5]), fmaxf(s[6], s[7])));
            #pragma unroll
            for (int off = 8; off > 0; off >>= 1)
                tmax = fmaxf(tmax, __shfl_xor_sync(0xffffffffu, tmax, off, 16));
            const float m_new = fmaxf(m_run[i], tmax);
            float es = 0.0f;
            #pragma unroll
            for (int u = 0; u < 8; ++u) es += __expf(s[u] - m_new);
            #pragma unroll
            for (int off = 8; off > 0; off >>= 1)
                es += __shfl_xor_sync(0xffffffffu, es, off, 16);
            l_run[i] = l_run[i] * __expf(m_run[i] - m_new) + es;
            m_run[i] = m_new;
        }
    }

    // park per-row stats for pass-2 (different thread mapping)
    if (tx == 0) {
        #pragma unroll
        for (int i = 0; i < 8; ++i) {
            sMx[8 * ty + i] = m_run[i];
            sLi[8 * ty + i] = 1.0f / l_run[i];
        }
    }
    __syncthreads();

    // ================= Pass 2: finalize p, out += p @ V =================
    const int ty2 = tid >> 3;   // q-row group (0..31) -> rows 4*ty2+i
    const int tx2 = tid & 7;    // d-col group (0..7)  -> cols 8*tx2+j

    float m2[4], il2[4];
    #pragma unroll
    for (int i = 0; i < 4; ++i) {
        m2[i]  = sMx[4 * ty2 + i];
        il2[i] = sLi[4 * ty2 + i];
    }

    float acc2[4][8];
    #pragma unroll
    for (int i = 0; i < 4; ++i)
        #pragma unroll
        for (int j = 0; j < 8; ++j) acc2[i][j] = 0.0f;

    for (int kt = 0; kt < S_LEN; kt += 128) {
        __syncthreads();
        // V tile [128k][64d] -> sV[k][d]
        #pragma unroll
        for (int it = 0; it < 8; ++it) {
            const int idx = tid + it * 256;
            const int r = idx >> 4;
            const int c = (idx & 15) * 4;
            float4 v = *(const float4*)(vp + (size_t)(kt + r) * D_HEAD + c);
            *(float4*)(sV + r * 68 + c) = v;
        }
        // scores: coalesced re-read, finalize p, write back + stage in sP[q][k]
        #pragma unroll
        for (int it = 0; it < 16; ++it) {
            const int idx = tid + it * 256;
            const int r = idx >> 5;
            const int c = (idx & 31) * 4;
            float4 s = *(const float4*)(pp + (size_t)r * S_LEN + kt + c);
            const float mr = sMx[r], il = sLi[r];
            float4 p;
            p.x = __expf(s.x - mr) * il;
            p.y = __expf(s.y - mr) * il;
            p.z = __expf(s.z - mr) * il;
            p.w = __expf(s.w - mr) * il;
            *(float4*)(pp + (size_t)r * S_LEN + kt + c) = p;
            *(float4*)(sP + r * 132 + c) = p;
        }
        __syncthreads();

        #pragma unroll 2
        for (int kk = 0; kk < 128; kk += 4) {
            float4 a4[4];
            #pragma unroll
            for (int i = 0; i < 4; ++i)
                a4[i] = *(const float4*)(sP + (4 * ty2 + i) * 132 + kk);
            #pragma unroll
            for (int u = 0; u < 4; ++u) {
                float4 b0 = *(const float4*)(sV + (kk + u) * 68 + 8 * tx2);
                float4 b1 = *(const float4*)(sV + (kk + u) * 68 + 8 * tx2 + 4);
                const float bv[8] = {b0.x, b0.y, b0.z, b0.w, b1.x, b1.y, b1.z, b1.w};
                #pragma unroll
                for (int i = 0; i < 4; ++i) {
                    const float av = ((const float*)&a4[i])[u];
                    #pragma unroll
                    for (int j = 0; j < 8; ++j)
                        acc2[i][j] += av * bv[j];
                }
            }
        }
    }

    #pragma unroll
    for (int i = 0; i < 4; ++i) {
        *(float4*)(op + (size_t)(4 * ty2 + i) * D_HEAD + 8 * tx2) =
            make_float4(acc2[i][0], acc2[i][1], acc2[i][2], acc2[i][3]);
        *(float4*)(op + (size_t)(4 * ty2 + i) * D_HEAD + 8 * tx2 + 4) =
            make_float4(acc2[i][4], acc2[i][5], acc2[i][6], acc2[i][7]);
    }
}

extern "C" void kernel_launch(void* const* d_in, const int* in_sizes, int n_in,
                              void* d_out, int out_size)
{
    const float* q = (const float*)d_in[0];
    const float* k = (const float*)d_in[1];
    const float* v = (const float*)d_in[2];
    const int*   m = (const int*)d_in[3];
    float* out = (float*)d_out;
    float* p   = out + (size_t)2 * 16 * 2048 * 64;

    const int smem_bytes = (256 + 128 * 132 + 128 * 68) * 4;  // 103424
    cudaFuncSetAttribute(attn_kernel,
                         cudaFuncAttributeMaxDynamicSharedMemorySize, smem_bytes);
    dim3 grid(S_LEN / TQ, 2 * 16);
    attn_kernel<<<grid, 256, smem_bytes>>>(q, k, v, m, out, p);
}

// round 12
// speedup vs baseline: 1.5736x; 1.5736x over previous
#include <cuda_runtime.h>
#include <cuda_bf16.h>

#define S_LEN 2048
#define TQ 64
#define TK 64
#define LOG2E 1.4426950408889634f

// smem byte offsets; padded bf16 strides for bank-conflict-free fragment loads
#define QS 72
#define KS 72
#define VS 74
#define OFF_QH 0
#define OFF_QL (OFF_QH + 64 * QS * 2)
#define OFF_KH (OFF_QL + 64 * QS * 2)
#define OFF_KL (OFF_KH + 64 * KS * 2)
#define OFF_VH (OFF_KL + 64 * KS * 2)
#define OFF_VL (OFF_VH + 64 * VS * 2)
#define SMEM_SZ (OFF_VL + 64 * VS * 2)   // 55808 B

__device__ __forceinline__ float ex2f(float x) {
    float r; asm("ex2.approx.ftz.f32 %0, %1;" : "=f"(r) : "f"(x)); return r;
}

// D += A * B  (m16n8k16, bf16 in, f32 accum)
__device__ __forceinline__ void mma16816(float d[4], const unsigned a[4],
                                         unsigned b0, unsigned b1) {
    asm volatile(
        "mma.sync.aligned.m16n8k16.row.col.f32.bf16.bf16.f32 "
        "{%0,%1,%2,%3}, {%4,%5,%6,%7}, {%8,%9}, {%0,%1,%2,%3};"
        : "+f"(d[0]), "+f"(d[1]), "+f"(d[2]), "+f"(d[3])
        : "r"(a[0]), "r"(a[1]), "r"(a[2]), "r"(a[3]), "r"(b0), "r"(b1));
}

// split (x,y) into hi/lo bf16x2 (low half = x)
__device__ __forceinline__ unsigned pack_split(float x, float y, unsigned& lo) {
    __nv_bfloat16 hx = __float2bfloat16(x), hy = __float2bfloat16(y);
    float rx = x - __bfloat162float(hx), ry = y - __bfloat162float(hy);
    __nv_bfloat16 lx = __float2bfloat16(rx), ly = __float2bfloat16(ry);
    lo = ((unsigned)__bfloat16_as_ushort(ly) << 16) | __bfloat16_as_ushort(lx);
    return ((unsigned)__bfloat16_as_ushort(hy) << 16) | __bfloat16_as_ushort(hx);
}

__global__ __launch_bounds__(128, 3)
void attn_mma(const float* __restrict__ Qg, const float* __restrict__ Kg,
              const float* __restrict__ Vg, const int* __restrict__ Mg,
              float* __restrict__ Out, float* __restrict__ Pg)
{
    extern __shared__ __align__(16) char sm[];
    const int tid = threadIdx.x, lane = tid & 31, wid = tid >> 5;
    const int g = lane >> 2, t = lane & 3;
    const int bh = blockIdx.x;           // 0..31 (b*16+h) — bh-major for mask L2 reuse
    const int q0 = blockIdx.y * TQ;
    const int wr = wid * 16;

    const float* qg = Qg + ((size_t)bh * S_LEN + q0) * 64;
    const float* kg = Kg + (size_t)bh * S_LEN * 64;
    const float* vg = Vg + (size_t)bh * S_LEN * 64;
    const int row0 = q0 + wr + g;
    const int* mp0 = Mg + (size_t)(bh >> 4) * S_LEN * S_LEN + (size_t)row0 * S_LEN;
    const int* mp8 = mp0 + 8 * S_LEN;
    float* pp0 = Pg + ((size_t)bh * S_LEN + row0) * S_LEN;
    float* pp8 = pp0 + 8 * S_LEN;
    float* op0 = Out + ((size_t)bh * S_LEN + row0) * 64;
    float* op8 = op0 + 8 * 64;

    // ---- Q fill: scale by 1/8, split hi/lo ----
    for (int i = tid; i < 64 * 16; i += 128) {
        int r = i >> 4, c = (i & 15) * 4;
        float4 v = *(const float4*)(qg + r * 64 + c);
        v.x *= 0.125f; v.y *= 0.125f; v.z *= 0.125f; v.w *= 0.125f;
        unsigned l0, l1;
        unsigned h0 = pack_split(v.x, v.y, l0), h1 = pack_split(v.z, v.w, l1);
        *(uint2*)(sm + OFF_QH + (r * QS + c) * 2) = make_uint2(h0, h1);
        *(uint2*)(sm + OFF_QL + (r * QS + c) * 2) = make_uint2(l0, l1);
    }

    const int acol = 2 * t;   // fragment k-col base

    // compute S tile (16 q-rows x 64 k-tokens per warp) into S[8][4]
    auto computeS = [&](float S[8][4]) {
        #pragma unroll
        for (int j = 0; j < 8; ++j)
            #pragma unroll
            for (int u = 0; u < 4; ++u) S[j][u] = 0.f;
        #pragma unroll
        for (int kc = 0; kc < 4; ++kc) {
            const int c = kc * 16 + acol;
            unsigned ah[4], al[4];
            ah[0] = *(const unsigned*)(sm + OFF_QH + ((wr + g) * QS + c) * 2);
            ah[1] = *(const unsigned*)(sm + OFF_QH + ((wr + g + 8) * QS + c) * 2);
            ah[2] = *(const unsigned*)(sm + OFF_QH + ((wr + g) * QS + c + 8) * 2);
            ah[3] = *(const unsigned*)(sm + OFF_QH + ((wr + g + 8) * QS + c + 8) * 2);
            al[0] = *(const unsigned*)(sm + OFF_QL + ((wr + g) * QS + c) * 2);
            al[1] = *(const unsigned*)(sm + OFF_QL + ((wr + g + 8) * QS + c) * 2);
            al[2] = *(const unsigned*)(sm + OFF_QL + ((wr + g) * QS + c + 8) * 2);
            al[3] = *(const unsigned*)(sm + OFF_QL + ((wr + g + 8) * QS + c + 8) * 2);
            #pragma unroll
            for (int j = 0; j < 8; ++j) {
                const int br = j * 8 + g;
                unsigned bh0 = *(const unsigned*)(sm + OFF_KH + (br * KS + c) * 2);
                unsigned bh1 = *(const unsigned*)(sm + OFF_KH + (br * KS + c + 8) * 2);
                unsigned bl0 = *(const unsigned*)(sm + OFF_KL + (br * KS + c) * 2);
                unsigned bl1 = *(const unsigned*)(sm + OFF_KL + (br * KS + c + 8) * 2);
                mma16816(S[j], ah, bh0, bh1);   // Qh*Kh
                mma16816(S[j], al, bh0, bh1);   // Ql*Kh
                mma16816(S[j], ah, bl0, bl1);   // Qh*Kl
            }
        }
    };

    auto fillK = [&](int kt) {
        for (int i = tid; i < 64 * 16; i += 128) {
            int r = i >> 4, c = (i & 15) * 4;
            float4 v = *(const float4*)(kg + (size_t)(kt + r) * 64 + c);
            unsigned l0, l1;
            unsigned h0 = pack_split(v.x, v.y, l0), h1 = pack_split(v.z, v.w, l1);
            *(uint2*)(sm + OFF_KH + (r * KS + c) * 2) = make_uint2(h0, h1);
            *(uint2*)(sm + OFF_KL + (r * KS + c) * 2) = make_uint2(l0, l1);
        }
    };
    auto fillV = [&](int kt) {   // transposed: sV[d][token]
        for (int i = tid; i < 64 * 16; i += 128) {
            int r = i >> 4, c = (i & 15) * 4;   // token r, d = c..c+3
            float4 v = *(const float4*)(vg + (size_t)(kt + r) * 64 + c);
            const float f[4] = {v.x, v.y, v.z, v.w};
            #pragma unroll
            for (int u = 0; u < 4; ++u) {
                __nv_bfloat16 h = __float2bfloat16(f[u]);
                __nv_bfloat16 l = __float2bfloat16(f[u] - __bfloat162float(h));
                *(__nv_bfloat16*)(sm + OFF_VH + ((c + u) * VS + r) * 2) = h;
                *(__nv_bfloat16*)(sm + OFF_VL + ((c + u) * VS + r) * 2) = l;
            }
        }
    };

    // ================= Pass A: row sums l =================
    float lA = 0.f, lB = 0.f;
    for (int kt = 0; kt < S_LEN; kt += TK) {
        __syncthreads();
        fillK(kt);
        __syncthreads();
        float S[8][4];
        computeS(S);
        #pragma unroll
        for (int j = 0; j < 8; ++j) {
            const int col = kt + j * 8 + acol;
            int2 m0 = *(const int2*)(mp0 + col);
            int2 m1 = *(const int2*)(mp8 + col);
            float e0 = m0.x ? ex2f(S[j][0] * LOG2E) : 0.f;
            float e1 = m0.y ? ex2f(S[j][1] * LOG2E) : 0.f;
            float e2 = m1.x ? ex2f(S[j][2] * LOG2E) : 0.f;
            float e3 = m1.y ? ex2f(S[j][3] * LOG2E) : 0.f;
            lA += e0 + e1;
            lB += e2 + e3;
        }
    }
    lA += __shfl_xor_sync(0xffffffffu, lA, 1);
    lA += __shfl_xor_sync(0xffffffffu, lA, 2);
    lB += __shfl_xor_sync(0xffffffffu, lB, 1);
    lB += __shfl_xor_sync(0xffffffffu, lB, 2);
    const float invA = 1.f / lA, invB = 1.f / lB;

    // ============ Pass B: recompute S, write p, O += p V ============
    float O[8][4];
    #pragma unroll
    for (int j = 0; j < 8; ++j)
        #pragma unroll
        for (int u = 0; u < 4; ++u) O[j][u] = 0.f;

    for (int kt = 0; kt < S_LEN; kt += TK) {
        __syncthreads();
        fillK(kt);
        fillV(kt);
        __syncthreads();
        float S[8][4];
        computeS(S);

        float pv[8][4];
        #pragma unroll
        for (int j = 0; j < 8; ++j) {
            const int col = kt + j * 8 + acol;
            int2 m0 = *(const int2*)(mp0 + col);
            int2 m1 = *(const int2*)(mp8 + col);
            pv[j][0] = m0.x ? ex2f(S[j][0] * LOG2E) * invA : 0.f;
            pv[j][1] = m0.y ? ex2f(S[j][1] * LOG2E) * invA : 0.f;
            pv[j][2] = m1.x ? ex2f(S[j][2] * LOG2E) * invB : 0.f;
            pv[j][3] = m1.y ? ex2f(S[j][3] * LOG2E) * invB : 0.f;
            *(float2*)(pp0 + col) = make_float2(pv[j][0], pv[j][1]);
            *(float2*)(pp8 + col) = make_float2(pv[j][2], pv[j][3]);
        }

        #pragma unroll
        for (int kc = 0; kc < 4; ++kc) {
            unsigned ah[4], al[4];
            ah[0] = pack_split(pv[2*kc][0],   pv[2*kc][1],   al[0]);
            ah[1] = pack_split(pv[2*kc][2],   pv[2*kc][3],   al[1]);
            ah[2] = pack_split(pv[2*kc+1][0], pv[2*kc+1][1], al[2]);
            ah[3] = pack_split(pv[2*kc+1][2], pv[2*kc+1][3], al[3]);
            const int tok = kc * 16 + acol;
            #pragma unroll
            for (int jd = 0; jd < 8; ++jd) {
                const int dr = jd * 8 + g;
                unsigned bh0 = *(const unsigned*)(sm + OFF_VH + (dr * VS + tok) * 2);
                unsigned bh1 = *(const unsigned*)(sm + OFF_VH + (dr * VS + tok + 8) * 2);
                unsigned bl0 = *(const unsigned*)(sm + OFF_VL + (dr * VS + tok) * 2);
                unsigned bl1 = *(const unsigned*)(sm + OFF_VL + (dr * VS + tok + 8) * 2);
                mma16816(O[jd], ah, bh0, bh1);   // Ph*Vh
                mma16816(O[jd], al, bh0, bh1);   // Pl*Vh
                mma16816(O[jd], ah, bl0, bl1);   // Ph*Vl
            }
        }
    }

    // ---- out (already normalized: A used p = e/l) ----
    #pragma unroll
    for (int jd = 0; jd < 8; ++jd) {
        *(float2*)(op0 + jd * 8 + acol) = make_float2(O[jd][0], O[jd][1]);
        *(float2*)(op8 + jd * 8 + acol) = make_float2(O[jd][2], O[jd][3]);
    }
}

extern "C" void kernel_launch(void* const* d_in, const int* in_sizes, int n_in,
                              void* d_out, int out_size)
{
    const float* q = (const float*)d_in[0];
    const float* k = (const float*)d_in[1];
    const float* v = (const float*)d_in[2];
    const int*   m = (const int*)d_in[3];
    float* out = (float*)d_out;
    float* p   = out + (size_t)2 * 16 * 2048 * 64;

    cudaFuncSetAttribute(attn_mma, cudaFuncAttributeMaxDynamicSharedMemorySize, SMEM_SZ);
    dim3 grid(2 * 16, S_LEN / TQ);   // bh-major: heads sharing mask run together
    attn_mma<<<grid, 128, SMEM_SZ>>>(q, k, v, m, out, p);
}

// round 13
// speedup vs baseline: 1.7544x; 1.1149x over previous
#include <cuda_runtime.h>
#include <cuda_bf16.h>

#define S_LEN 2048
#define TQ 64
#define TK 64
#define LOG2E 1.4426950408889634f

// padded bf16 stride 72 (144 B): 16B-aligned rows, conflict-free for ldmatrix
#define QS 72
#define KS 72
#define VS 72
#define OFF_QH 0
#define OFF_QL (64 * QS * 2)
#define OFF_KH (2 * 64 * QS * 2)
#define OFF_KL (3 * 64 * QS * 2)
#define OFF_VH OFF_QH            // pass-B V aliases pass-A Q (dead by then)
#define OFF_VL OFF_QL
#define SMEM_SZ (4 * 64 * 72 * 2)   // 36864 B

__device__ __forceinline__ float ex2f(float x) {
    float r; asm("ex2.approx.ftz.f32 %0, %1;" : "=f"(r) : "f"(x)); return r;
}
__device__ __forceinline__ unsigned smem_u32(const void* p) {
    unsigned a;
    asm("{ .reg .u64 t; cvta.to.shared.u64 t, %1; cvt.u32.u64 %0, t; }" : "=r"(a) : "l"(p));
    return a;
}
// D += A * B  (m16n8k16, bf16 in, f32 accum)
__device__ __forceinline__ void mma16816(float d[4], const unsigned a[4],
                                         unsigned b0, unsigned b1) {
    asm volatile(
        "mma.sync.aligned.m16n8k16.row.col.f32.bf16.bf16.f32 "
        "{%0,%1,%2,%3}, {%4,%5,%6,%7}, {%8,%9}, {%0,%1,%2,%3};"
        : "+f"(d[0]), "+f"(d[1]), "+f"(d[2]), "+f"(d[3])
        : "r"(a[0]), "r"(a[1]), "r"(a[2]), "r"(a[3]), "r"(b0), "r"(b1));
}
#define LDSM4(r, a) asm volatile( \
    "ldmatrix.sync.aligned.m8n8.x4.shared.b16 {%0,%1,%2,%3}, [%4];" \
    : "=r"((r)[0]), "=r"((r)[1]), "=r"((r)[2]), "=r"((r)[3]) : "r"(a))

// split (x,y) into hi/lo bf16x2 (low half = x)
__device__ __forceinline__ unsigned pack_split(float x, float y, unsigned& lo) {
    __nv_bfloat16 hx = __float2bfloat16(x), hy = __float2bfloat16(y);
    float rx = x - __bfloat162float(hx), ry = y - __bfloat162float(hy);
    __nv_bfloat16 lx = __float2bfloat16(rx), ly = __float2bfloat16(ry);
    lo = ((unsigned)__bfloat16_as_ushort(ly) << 16) | __bfloat16_as_ushort(lx);
    return ((unsigned)__bfloat16_as_ushort(hy) << 16) | __bfloat16_as_ushort(hx);
}

__global__ __launch_bounds__(128, 4)
void attn_mma(const float* __restrict__ Qg, const float* __restrict__ Kg,
              const float* __restrict__ Vg, const int* __restrict__ Mg,
              float* __restrict__ Out, float* __restrict__ Pg)
{
    extern __shared__ __align__(16) char sm[];
    const unsigned sb = smem_u32(sm);
    const int tid = threadIdx.x, lane = tid & 31, wid = tid >> 5;
    const int g = lane >> 2, t = lane & 3;
    const int bh = blockIdx.x;
    const int q0 = blockIdx.y * TQ;
    const int wr = wid * 16;
    const int acol = 2 * t;

    // per-lane ldmatrix offsets (matrix = lane>>3)
    const int qrow = (lane & 7) + ((lane >> 3) & 1) * 8;   // + (m&1)*8
    const int qcol = (lane >> 4) * 8;                       // + (m>>1)*8
    const int krow = (lane & 7) + (lane >> 4) * 8;          // + (m>>1)*8
    const int kcol = ((lane >> 3) & 1) * 8;                 // + (m&1)*8

    const float* qg = Qg + ((size_t)bh * S_LEN + q0) * 64;
    const float* kg = Kg + (size_t)bh * S_LEN * 64;
    const float* vg = Vg + (size_t)bh * S_LEN * 64;
    const int row0 = q0 + wr + g;
    const int* mp0 = Mg + (size_t)(bh >> 4) * S_LEN * S_LEN + (size_t)row0 * S_LEN;
    const int* mp8 = mp0 + 8 * S_LEN;
    float* pp0 = Pg + ((size_t)bh * S_LEN + row0) * S_LEN;
    float* pp8 = pp0 + 8 * S_LEN;
    float* op0 = Out + ((size_t)bh * S_LEN + row0) * 64;
    float* op8 = op0 + 8 * 64;

    // ---- Q fill: scale by 1/8, split hi/lo ----
    for (int i = tid; i < 64 * 16; i += 128) {
        int r = i >> 4, c = (i & 15) * 4;
        float4 v = *(const float4*)(qg + r * 64 + c);
        v.x *= 0.125f; v.y *= 0.125f; v.z *= 0.125f; v.w *= 0.125f;
        unsigned l0, l1;
        unsigned h0 = pack_split(v.x, v.y, l0), h1 = pack_split(v.z, v.w, l1);
        *(uint2*)(sm + OFF_QH + (r * QS + c) * 2) = make_uint2(h0, h1);
        *(uint2*)(sm + OFF_QL + (r * QS + c) * 2) = make_uint2(l0, l1);
    }

    // ================= Pass A: S = QK^T, e = mask*exp(s), row sums =================
    float lA = 0.f, lB = 0.f;
    for (int kt = 0; kt < S_LEN; kt += TK) {
        __syncthreads();
        for (int i = tid; i < 64 * 16; i += 128) {   // K fill (split)
            int r = i >> 4, c = (i & 15) * 4;
            float4 v = *(const float4*)(kg + (size_t)(kt + r) * 64 + c);
            unsigned l0, l1;
            unsigned h0 = pack_split(v.x, v.y, l0), h1 = pack_split(v.z, v.w, l1);
            *(uint2*)(sm + OFF_KH + (r * KS + c) * 2) = make_uint2(h0, h1);
            *(uint2*)(sm + OFF_KL + (r * KS + c) * 2) = make_uint2(l0, l1);
        }
        __syncthreads();

        float S[8][4];
        #pragma unroll
        for (int j = 0; j < 8; ++j)
            #pragma unroll
            for (int u = 0; u < 4; ++u) S[j][u] = 0.f;

        #pragma unroll
        for (int kc = 0; kc < 4; ++kc) {
            unsigned ah[4], al[4];
            const unsigned qa = sb + OFF_QH + ((wr + qrow) * QS + kc * 16 + qcol) * 2;
            LDSM4(ah, qa);
            LDSM4(al, qa + (OFF_QL - OFF_QH));
            #pragma unroll
            for (int jp = 0; jp < 4; ++jp) {
                unsigned kh[4], kl[4];
                const unsigned ka = sb + OFF_KH +
                    ((jp * 16 + krow) * KS + kc * 16 + kcol) * 2;
                LDSM4(kh, ka);
                LDSM4(kl, ka + (OFF_KL - OFF_KH));
                mma16816(S[2*jp],   ah, kh[0], kh[1]);
                mma16816(S[2*jp],   al, kh[0], kh[1]);
                mma16816(S[2*jp],   ah, kl[0], kl[1]);
                mma16816(S[2*jp+1], ah, kh[2], kh[3]);
                mma16816(S[2*jp+1], al, kh[2], kh[3]);
                mma16816(S[2*jp+1], ah, kl[2], kl[3]);
            }
        }

        #pragma unroll
        for (int j = 0; j < 8; ++j) {
            const int col = kt + j * 8 + acol;
            int2 m0 = *(const int2*)(mp0 + col);
            int2 m1 = *(const int2*)(mp8 + col);
            float e0 = m0.x ? ex2f(S[j][0] * LOG2E) : 0.f;
            float e1 = m0.y ? ex2f(S[j][1] * LOG2E) : 0.f;
            float e2 = m1.x ? ex2f(S[j][2] * LOG2E) : 0.f;
            float e3 = m1.y ? ex2f(S[j][3] * LOG2E) : 0.f;
            lA += e0 + e1;
            lB += e2 + e3;
            *(float2*)(pp0 + col) = make_float2(e0, e1);   // raw e (scratch)
            *(float2*)(pp8 + col) = make_float2(e2, e3);
        }
    }
    lA += __shfl_xor_sync(0xffffffffu, lA, 1);
    lA += __shfl_xor_sync(0xffffffffu, lA, 2);
    lB += __shfl_xor_sync(0xffffffffu, lB, 1);
    lB += __shfl_xor_sync(0xffffffffu, lB, 2);
    const float invA = 1.f / lA, invB = 1.f / lB;

    // ====== Pass B: read e, write p = e/l, O += p V (no S recompute) ======
    float O[8][4];
    #pragma unroll
    for (int j = 0; j < 8; ++j)
        #pragma unroll
        for (int u = 0; u < 4; ++u) O[j][u] = 0.f;

    for (int kt = 0; kt < S_LEN; kt += TK) {
        __syncthreads();
        for (int i = tid; i < 64 * 16; i += 128) {   // V fill, transposed [d][tok]
            int r = i >> 4, c = (i & 15) * 4;
            float4 v = *(const float4*)(vg + (size_t)(kt + r) * 64 + c);
            const float f[4] = {v.x, v.y, v.z, v.w};
            #pragma unroll
            for (int u = 0; u < 4; ++u) {
                __nv_bfloat16 h = __float2bfloat16(f[u]);
                __nv_bfloat16 l = __float2bfloat16(f[u] - __bfloat162float(h));
                *(__nv_bfloat16*)(sm + OFF_VH + ((c + u) * VS + r) * 2) = h;
                *(__nv_bfloat16*)(sm + OFF_VL + ((c + u) * VS + r) * 2) = l;
            }
        }
        __syncthreads();

        #pragma unroll
        for (int kc = 0; kc < 4; ++kc) {
            const int colA = kt + kc * 16 + acol;    // tokens for a0/a1
            const int colB = colA + 8;               // tokens for a2/a3
            float2 ea0 = *(const float2*)(pp0 + colA);
            float2 ea1 = *(const float2*)(pp8 + colA);
            float2 eb0 = *(const float2*)(pp0 + colB);
            float2 eb1 = *(const float2*)(pp8 + colB);
            float p00 = ea0.x * invA, p01 = ea0.y * invA;
            float p08 = ea1.x * invB, p09 = ea1.y * invB;
            float p10 = eb0.x * invA, p11 = eb0.y * invA;
            float p18 = eb1.x * invB, p19 = eb1.y * invB;
            *(float2*)(pp0 + colA) = make_float2(p00, p01);   // final p
            *(float2*)(pp8 + colA) = make_float2(p08, p09);
            *(float2*)(pp0 + colB) = make_float2(p10, p11);
            *(float2*)(pp8 + colB) = make_float2(p18, p19);

            unsigned ah[4], al[4];
            ah[0] = pack_split(p00, p01, al[0]);
            ah[1] = pack_split(p08, p09, al[1]);
            ah[2] = pack_split(p10, p11, al[2]);
            ah[3] = pack_split(p18, p19, al[3]);

            #pragma unroll
            for (int jdp = 0; jdp < 4; ++jdp) {
                unsigned vh[4], vl[4];
                const unsigned va = sb + OFF_VH +
                    ((jdp * 16 + krow) * VS + kc * 16 + kcol) * 2;
                LDSM4(vh, va);
                LDSM4(vl, va + (OFF_VL - OFF_VH));
                mma16816(O[2*jdp],   ah, vh[0], vh[1]);
                mma16816(O[2*jdp],   al, vh[0], vh[1]);
                mma16816(O[2*jdp],   ah, vl[0], vl[1]);
                mma16816(O[2*jdp+1], ah, vh[2], vh[3]);
                mma16816(O[2*jdp+1], al, vh[2], vh[3]);
                mma16816(O[2*jdp+1], ah, vl[2], vl[3]);
            }
        }
    }

    // ---- out (already normalized) ----
    #pragma unroll
    for (int jd = 0; jd < 8; ++jd) {
        *(float2*)(op0 + jd * 8 + acol) = make_float2(O[jd][0], O[jd][1]);
        *(float2*)(op8 + jd * 8 + acol) = make_float2(O[jd][2], O[jd][3]);
    }
}

extern "C" void kernel_launch(void* const* d_in, const int* in_sizes, int n_in,
                              void* d_out, int out_size)
{
    const float* q = (const float*)d_in[0];
    const float* k = (const float*)d_in[1];
    const float* v = (const float*)d_in[2];
    const int*   m = (const int*)d_in[3];
    float* out = (float*)d_out;
    float* p   = out + (size_t)2 * 16 * 2048 * 64;

    cudaFuncSetAttribute(attn_mma, cudaFuncAttributeMaxDynamicSharedMemorySize, SMEM_SZ);
    dim3 grid(2 * 16, S_LEN / TQ);   // bh-major: heads sharing mask run together
    attn_mma<<<grid, 128, SMEM_SZ>>>(q, k, v, m, out, p);
}